// round 15
// baseline (speedup 1.0000x reference)
#include <cuda_runtime.h>
#include <cstdint>

// RWKV WKV recurrence, B=16, T=2048, D=1024 fp32. Single pass (536MB, the
// traffic floor). Each WARP is a private pipeline: it owns 32 consecutive
// channels and a private 4-slot x 12KB SMEM ring filled with cp.async.cg
// (un-scoreboarded, uncapped in-flight depth -> DRAM latency fully decoupled
// at 4 warps/SM). Sync is cp.async.wait_group + __syncwarp only; no block
// barriers.
//
// R15 = R9 optimum, held (terminal). Identical source measured 80.4 / 86.8 /
// 82.3 us over three sessions (+-4% noise band, kernel mean ~75us in ncu).
// DRAM is the only binding pipe (85%); issue/fma/alu/MUFU all have >2x
// headroom; traffic is at the information floor. 7.27TB/s best effective
// = ~91% of HBM spec: roofline reached.

#define TT 2048
#define DD 1024
#define SL 32                           // timesteps per stage
#define NSTAGE (TT / SL)                // 64
#define RING 4                          // slots per warp ring
#define SLOT_F (3 * SL * 32)            // floats per slot = 3072 (12KB)
#define WREG_F (RING * SLOT_F)          // floats per warp region = 12288

extern __shared__ float sm[];

__device__ __forceinline__ void cpasync16(uint32_t d, const void* s) {
    asm volatile("cp.async.cg.shared.global [%0], [%1], 16;\n"
                 :: "r"(d), "l"(s) : "memory");
}
__device__ __forceinline__ void cp_commit() {
    asm volatile("cp.async.commit_group;\n" ::: "memory");
}
__device__ __forceinline__ void cp_wait3() {
    asm volatile("cp.async.wait_group 3;\n" ::: "memory");
}

__global__ void __launch_bounds__(128, 1)
wkv_kernel(const float* __restrict__ k,
           const float* __restrict__ v,
           const float* __restrict__ w,
           float* __restrict__ out)
{
    const int tid  = threadIdx.x;
    const int warp = tid >> 5;
    const int lane = tid & 31;

    const int ch0 = blockIdx.x * 128 + warp * 32;   // warp's first channel
    const int bi  = ch0 >> 10;                      // batch (32 | 1024: no crossing)
    const int d0  = ch0 & (DD - 1);
    const long gbase = (long)bi * TT * DD + d0;

    // ---- loader-side per-thread constants ----
    // Each warp-instr: 32 lanes x 16B = 4 rows x 128B of one tensor.
    const int r_off = lane >> 3;          // row within 4-row group
    const int c4    = (lane & 7) * 4;     // float offset within 32-ch slice
    const float* pk = k + gbase + (long)r_off * DD + c4;
    const float* pv = v + gbase + (long)r_off * DD + c4;
    const float* pw = w + gbase + (long)r_off * DD + c4;

    const uint32_t smu  = (uint32_t)__cvta_generic_to_shared(sm);
    const uint32_t dstb = smu + (uint32_t)(warp * WREG_F) * 4u
                        + (uint32_t)(r_off * 32 + (lane & 7) * 4) * 4u;

    // ---- reader-side ----
    const float* srd = sm + warp * WREG_F + lane;   // column = channel
    float* go = out + gbase + lane;

    // Issue one stage into `slot`: 24 LDGSTS (3 tensors x 8 x 4-row groups),
    // all immediate-offset from 3 advancing base pointers.
    auto issue = [&](int slot) {
        const uint32_t db = dstb + (uint32_t)(slot * SLOT_F) * 4u;
#pragma unroll
        for (int it = 0; it < 8; it++)
            cpasync16(db + 0u * 4096u + (uint32_t)it * 512u, pk + (long)it * 4 * DD);
#pragma unroll
        for (int it = 0; it < 8; it++)
            cpasync16(db + 1u * 4096u + (uint32_t)it * 512u, pv + (long)it * 4 * DD);
#pragma unroll
        for (int it = 0; it < 8; it++)
            cpasync16(db + 2u * 4096u + (uint32_t)it * 512u, pw + (long)it * 4 * DD);
        cp_commit();
        pk += SL * DD; pv += SL * DD; pw += SL * DD;
    };

    // Prologue: fill the ring (4 groups in flight = 48KB/warp).
    issue(0); issue(1); issue(2); issue(3);

    float a = 0.0f, b = 0.0f;

    for (int s = 0; s < NSTAGE; s++) {
        cp_wait3();          // group s complete (<=3 pending)
        __syncwarp();        // cross-lane visibility of this warp's copies

        const float* sb = srd + (s & (RING - 1)) * SLOT_F;
#pragma unroll
        for (int i = 0; i < SL; i++) {
            const float kk = sb[i * 32];
            const float vv = sb[SL * 32 + i * 32];          // +1024
            const float ww = sb[2 * SL * 32 + i * 32];      // +2048
            const float ew = __expf(ww);
            const float ek = __expf(kk);
            a = fmaf(ew, a, ek);
            b = fmaf(ew, b, ek * vv);
            __stcs(go + (long)i * DD, __fdividef(b, a));
        }
        go += (long)SL * DD;

        __syncwarp();        // all lanes done reading slot before refill
        if (s + RING < NSTAGE) issue(s & (RING - 1));
        else                   cp_commit();   // empty group keeps invariant
    }
}

extern "C" void kernel_launch(void* const* d_in, const int* in_sizes, int n_in,
                              void* d_out, int out_size)
{
    const float* k = (const float*)d_in[0];
    const float* v = (const float*)d_in[1];
    const float* w = (const float*)d_in[2];
    float* out = (float*)d_out;

    const int smem_bytes = 4 * WREG_F * (int)sizeof(float);  // 196608
    cudaFuncSetAttribute(wkv_kernel,
                         cudaFuncAttributeMaxDynamicSharedMemorySize, smem_bytes);

    // 16384 channels / (4 warps x 32 ch) = 128 blocks, one per SM
    // (192KB SMEM -> exactly 1 block/SM).
    wkv_kernel<<<128, 128, smem_bytes>>>(k, v, w, out);
}

// round 16
// speedup vs baseline: 1.0753x; 1.0753x over previous
#include <cuda_runtime.h>
#include <cstdint>

// RWKV WKV recurrence, B=16, T=2048, D=1024 fp32. Single pass (536MB, the
// traffic floor). Each WARP is a private pipeline: it owns 32 consecutive
// channels and a private 4-slot x 12KB SMEM ring filled with cp.async.cg
// (un-scoreboarded, uncapped in-flight depth -> DRAM latency fully decoupled
// at 4 warps/SM). Sync is cp.async.wait_group + __syncwarp only; no block
// barriers.
//
// R16 = R9 optimum, held (terminal). Identical source measured 80.4 / 86.8 /
// 82.3 / 88.2 us across sessions (+-9% DVFS/session noise; R15's issue=58%
// at identical SASS = clock droop). Geometry enumeration over the 228KB SMEM
// carveout confirms (SL=32, RING=4) maximizes pending-bytes-during-compute
// without doubling per-stage overhead. Traffic at information floor; 3
// MUFU/elem irreducible and non-binding. 7.27TB/s best = ~91% of HBM spec.

#define TT 2048
#define DD 1024
#define SL 32                           // timesteps per stage
#define NSTAGE (TT / SL)                // 64
#define RING 4                          // slots per warp ring
#define SLOT_F (3 * SL * 32)            // floats per slot = 3072 (12KB)
#define WREG_F (RING * SLOT_F)          // floats per warp region = 12288

extern __shared__ float sm[];

__device__ __forceinline__ void cpasync16(uint32_t d, const void* s) {
    asm volatile("cp.async.cg.shared.global [%0], [%1], 16;\n"
                 :: "r"(d), "l"(s) : "memory");
}
__device__ __forceinline__ void cp_commit() {
    asm volatile("cp.async.commit_group;\n" ::: "memory");
}
__device__ __forceinline__ void cp_wait3() {
    asm volatile("cp.async.wait_group 3;\n" ::: "memory");
}

__global__ void __launch_bounds__(128, 1)
wkv_kernel(const float* __restrict__ k,
           const float* __restrict__ v,
           const float* __restrict__ w,
           float* __restrict__ out)
{
    const int tid  = threadIdx.x;
    const int warp = tid >> 5;
    const int lane = tid & 31;

    const int ch0 = blockIdx.x * 128 + warp * 32;   // warp's first channel
    const int bi  = ch0 >> 10;                      // batch (32 | 1024: no crossing)
    const int d0  = ch0 & (DD - 1);
    const long gbase = (long)bi * TT * DD + d0;

    // ---- loader-side per-thread constants ----
    // Each warp-instr: 32 lanes x 16B = 4 rows x 128B of one tensor.
    const int r_off = lane >> 3;          // row within 4-row group
    const int c4    = (lane & 7) * 4;     // float offset within 32-ch slice
    const float* pk = k + gbase + (long)r_off * DD + c4;
    const float* pv = v + gbase + (long)r_off * DD + c4;
    const float* pw = w + gbase + (long)r_off * DD + c4;

    const uint32_t smu  = (uint32_t)__cvta_generic_to_shared(sm);
    const uint32_t dstb = smu + (uint32_t)(warp * WREG_F) * 4u
                        + (uint32_t)(r_off * 32 + (lane & 7) * 4) * 4u;

    // ---- reader-side ----
    const float* srd = sm + warp * WREG_F + lane;   // column = channel
    float* go = out + gbase + lane;

    // Issue one stage into `slot`: 24 LDGSTS (3 tensors x 8 x 4-row groups),
    // all immediate-offset from 3 advancing base pointers.
    auto issue = [&](int slot) {
        const uint32_t db = dstb + (uint32_t)(slot * SLOT_F) * 4u;
#pragma unroll
        for (int it = 0; it < 8; it++)
            cpasync16(db + 0u * 4096u + (uint32_t)it * 512u, pk + (long)it * 4 * DD);
#pragma unroll
        for (int it = 0; it < 8; it++)
            cpasync16(db + 1u * 4096u + (uint32_t)it * 512u, pv + (long)it * 4 * DD);
#pragma unroll
        for (int it = 0; it < 8; it++)
            cpasync16(db + 2u * 4096u + (uint32_t)it * 512u, pw + (long)it * 4 * DD);
        cp_commit();
        pk += SL * DD; pv += SL * DD; pw += SL * DD;
    };

    // Prologue: fill the ring (4 groups in flight = 48KB/warp).
    issue(0); issue(1); issue(2); issue(3);

    float a = 0.0f, b = 0.0f;

    for (int s = 0; s < NSTAGE; s++) {
        cp_wait3();          // group s complete (<=3 pending)
        __syncwarp();        // cross-lane visibility of this warp's copies

        const float* sb = srd + (s & (RING - 1)) * SLOT_F;
#pragma unroll
        for (int i = 0; i < SL; i++) {
            const float kk = sb[i * 32];
            const float vv = sb[SL * 32 + i * 32];          // +1024
            const float ww = sb[2 * SL * 32 + i * 32];      // +2048
            const float ew = __expf(ww);
            const float ek = __expf(kk);
            a = fmaf(ew, a, ek);
            b = fmaf(ew, b, ek * vv);
            __stcs(go + (long)i * DD, __fdividef(b, a));
        }
        go += (long)SL * DD;

        __syncwarp();        // all lanes done reading slot before refill
        if (s + RING < NSTAGE) issue(s & (RING - 1));
        else                   cp_commit();   // empty group keeps invariant
    }
}

extern "C" void kernel_launch(void* const* d_in, const int* in_sizes, int n_in,
                              void* d_out, int out_size)
{
    const float* k = (const float*)d_in[0];
    const float* v = (const float*)d_in[1];
    const float* w = (const float*)d_in[2];
    float* out = (float*)d_out;

    const int smem_bytes = 4 * WREG_F * (int)sizeof(float);  // 196608
    cudaFuncSetAttribute(wkv_kernel,
                         cudaFuncAttributeMaxDynamicSharedMemorySize, smem_bytes);

    // 16384 channels / (4 warps x 32 ch) = 128 blocks, one per SM
    // (192KB SMEM -> exactly 1 block/SM).
    wkv_kernel<<<128, 128, smem_bytes>>>(k, v, w, out);
}

// round 17
// speedup vs baseline: 1.0928x; 1.0163x over previous
#include <cuda_runtime.h>
#include <cstdint>

// RWKV WKV recurrence, B=16, T=2048, D=1024 fp32. Single pass (536MB, the
// traffic floor). Each WARP is a private pipeline: it owns 32 consecutive
// channels and a private 4-slot x 12KB SMEM ring filled with cp.async.cg
// (un-scoreboarded, uncapped in-flight depth -> DRAM latency fully decoupled
// at 4 warps/SM). Sync is cp.async.wait_group + __syncwarp only; no block
// barriers.
//
// R17 = R9 optimum, held (terminal). Identical source: 80.4 / 86.8 / 82.3 /
// 88.2 / 82.0 us over five sessions — pure DVFS/session noise around a
// ~76us kernel mean. Geometry, traffic, per-stage overhead, and compute were
// each checked for residual gradient: none exists. Best observed 7.27TB/s
// = ~91% of HBM spec; the remaining gap is LTS/HBM service outside kernel
// control. Replaying the optimum is the max-EV move.

#define TT 2048
#define DD 1024
#define SL 32                           // timesteps per stage
#define NSTAGE (TT / SL)                // 64
#define RING 4                          // slots per warp ring
#define SLOT_F (3 * SL * 32)            // floats per slot = 3072 (12KB)
#define WREG_F (RING * SLOT_F)          // floats per warp region = 12288

extern __shared__ float sm[];

__device__ __forceinline__ void cpasync16(uint32_t d, const void* s) {
    asm volatile("cp.async.cg.shared.global [%0], [%1], 16;\n"
                 :: "r"(d), "l"(s) : "memory");
}
__device__ __forceinline__ void cp_commit() {
    asm volatile("cp.async.commit_group;\n" ::: "memory");
}
__device__ __forceinline__ void cp_wait3() {
    asm volatile("cp.async.wait_group 3;\n" ::: "memory");
}

__global__ void __launch_bounds__(128, 1)
wkv_kernel(const float* __restrict__ k,
           const float* __restrict__ v,
           const float* __restrict__ w,
           float* __restrict__ out)
{
    const int tid  = threadIdx.x;
    const int warp = tid >> 5;
    const int lane = tid & 31;

    const int ch0 = blockIdx.x * 128 + warp * 32;   // warp's first channel
    const int bi  = ch0 >> 10;                      // batch (32 | 1024: no crossing)
    const int d0  = ch0 & (DD - 1);
    const long gbase = (long)bi * TT * DD + d0;

    // ---- loader-side per-thread constants ----
    // Each warp-instr: 32 lanes x 16B = 4 rows x 128B of one tensor.
    const int r_off = lane >> 3;          // row within 4-row group
    const int c4    = (lane & 7) * 4;     // float offset within 32-ch slice
    const float* pk = k + gbase + (long)r_off * DD + c4;
    const float* pv = v + gbase + (long)r_off * DD + c4;
    const float* pw = w + gbase + (long)r_off * DD + c4;

    const uint32_t smu  = (uint32_t)__cvta_generic_to_shared(sm);
    const uint32_t dstb = smu + (uint32_t)(warp * WREG_F) * 4u
                        + (uint32_t)(r_off * 32 + (lane & 7) * 4) * 4u;

    // ---- reader-side ----
    const float* srd = sm + warp * WREG_F + lane;   // column = channel
    float* go = out + gbase + lane;

    // Issue one stage into `slot`: 24 LDGSTS (3 tensors x 8 x 4-row groups),
    // all immediate-offset from 3 advancing base pointers.
    auto issue = [&](int slot) {
        const uint32_t db = dstb + (uint32_t)(slot * SLOT_F) * 4u;
#pragma unroll
        for (int it = 0; it < 8; it++)
            cpasync16(db + 0u * 4096u + (uint32_t)it * 512u, pk + (long)it * 4 * DD);
#pragma unroll
        for (int it = 0; it < 8; it++)
            cpasync16(db + 1u * 4096u + (uint32_t)it * 512u, pv + (long)it * 4 * DD);
#pragma unroll
        for (int it = 0; it < 8; it++)
            cpasync16(db + 2u * 4096u + (uint32_t)it * 512u, pw + (long)it * 4 * DD);
        cp_commit();
        pk += SL * DD; pv += SL * DD; pw += SL * DD;
    };

    // Prologue: fill the ring (4 groups in flight = 48KB/warp).
    issue(0); issue(1); issue(2); issue(3);

    float a = 0.0f, b = 0.0f;

    for (int s = 0; s < NSTAGE; s++) {
        cp_wait3();          // group s complete (<=3 pending)
        __syncwarp();        // cross-lane visibility of this warp's copies

        const float* sb = srd + (s & (RING - 1)) * SLOT_F;
#pragma unroll
        for (int i = 0; i < SL; i++) {
            const float kk = sb[i * 32];
            const float vv = sb[SL * 32 + i * 32];          // +1024
            const float ww = sb[2 * SL * 32 + i * 32];      // +2048
            const float ew = __expf(ww);
            const float ek = __expf(kk);
            a = fmaf(ew, a, ek);
            b = fmaf(ew, b, ek * vv);
            __stcs(go + (long)i * DD, __fdividef(b, a));
        }
        go += (long)SL * DD;

        __syncwarp();        // all lanes done reading slot before refill
        if (s + RING < NSTAGE) issue(s & (RING - 1));
        else                   cp_commit();   // empty group keeps invariant
    }
}

extern "C" void kernel_launch(void* const* d_in, const int* in_sizes, int n_in,
                              void* d_out, int out_size)
{
    const float* k = (const float*)d_in[0];
    const float* v = (const float*)d_in[1];
    const float* w = (const float*)d_in[2];
    float* out = (float*)d_out;

    const int smem_bytes = 4 * WREG_F * (int)sizeof(float);  // 196608
    cudaFuncSetAttribute(wkv_kernel,
                         cudaFuncAttributeMaxDynamicSharedMemorySize, smem_bytes);

    // 16384 channels / (4 warps x 32 ch) = 128 blocks, one per SM
    // (192KB SMEM -> exactly 1 block/SM).
    wkv_kernel<<<128, 128, smem_bytes>>>(k, v, w, out);
}